// round 17
// baseline (speedup 1.0000x reference)
#include <cuda_runtime.h>
#include <cstdint>

// SimpleZoneODE — GCN layers are dead code. Effective computation per row r:
//   c1 = bd1 + person@Wd1[32:40] + timeMLP(t)@Wd1[40:56]            [64]
//   h1 = relu(ze[r]@Wd1[0:32] + c1); h2 = relu(h1@Wd2+bd2); out = h2@Wd3+bd3
// R9 (resubmit after infra timeout): column-split. 2 rows/thread caps the
// chip at 10.5 warps/SM (total threads = rows/2, invariant to launch
// geometry) -> latency-bound at issue 24%. Add threads along COLUMNS:
// 256-thr blocks, 256 rows/block, thread = (2 rows) x (half the cols).
// Warps double to 21/SM while weight LDS per row stays amortized. Layer
// boundaries exchange activations via padded smem buffers. Dynamic smem
// 90.6KB, launch_bounds(256,2).

typedef unsigned long long ull;

static __device__ __forceinline__ ull fma2(ull a, ull b, ull c) {
    ull d;
    asm("fma.rn.f32x2 %0, %1, %2, %3;" : "=l"(d) : "l"(a), "l"(b), "l"(c));
    return d;
}
static __device__ __forceinline__ ull pack2(float x, float y) {
    ull r;
    asm("mov.b64 %0, {%1, %2};" : "=l"(r) : "f"(x), "f"(y));
    return r;
}
static __device__ __forceinline__ float2 unpack2(ull v) {
    float2 r;
    asm("mov.b64 {%0, %1}, %2;" : "=f"(r.x), "=f"(r.y) : "l"(v));
    return r;
}
static __device__ __forceinline__ void cp16(uint32_t smem, const void* g) {
    asm volatile("cp.async.cg.shared.global [%0], [%1], 16;" :: "r"(smem), "l"(g));
}

// smem layout (bytes):
//   [0)      sW1  1024 ull (Wd1 rows 0..31, [k][colpair])
//   [8192)   sW2  1024 ull
//   [16384)  sW3   512 ull
//   [20480)  sB2    16 ull
//   [20608)  sB3    16 ull
//   [20736)  sC1    64 float
//   [20992)  sX   256*34 ull  (h1 exchange; reused at stride 18 for h2)
#define SMEM_TOTAL (20992 + 256 * 34 * 8)

__global__ __launch_bounds__(256, 2) void zone_split_kernel(
    const float* __restrict__ ze,     // [n,32]
    const float* __restrict__ t,      // [1]
    const float* __restrict__ person, // [8]
    const float* __restrict__ Wt1,    // [1,16]
    const float* __restrict__ bt1,    // [16]
    const float* __restrict__ Wt2,    // [16,16]
    const float* __restrict__ bt2,    // [16]
    const float* __restrict__ Wd1,    // [56,64]
    const float* __restrict__ bd1,    // [64]
    const float* __restrict__ Wd2,    // [64,32]
    const float* __restrict__ bd2,    // [32]
    const float* __restrict__ Wd3,    // [32,32]
    const float* __restrict__ bd3,    // [32]
    float* __restrict__ out,          // [n,32]
    int n)
{
    extern __shared__ __align__(16) char smem[];
    ull*   sW1  = (ull*)(smem);
    ull*   sW2  = (ull*)(smem + 8192);
    ull*   sW3  = (ull*)(smem + 16384);
    ull*   sB2  = (ull*)(smem + 20480);
    ull*   sB3  = (ull*)(smem + 20608);
    float* sC1f = (float*)(smem + 20736);
    ull*   sX   = (ull*)(smem + 20992);

    const int tid = threadIdx.x;  // 0..255

    // ---- Parallel prologue ----
    if (tid >= 64 && tid < 128) {
        // Stage all weights via cp.async.
        const int s = tid - 64;  // 0..63
        const uint32_t a1 = (uint32_t)__cvta_generic_to_shared(sW1);
        const uint32_t a2 = (uint32_t)__cvta_generic_to_shared(sW2);
        const uint32_t a3 = (uint32_t)__cvta_generic_to_shared(sW3);
        const char* g1 = (const char*)Wd1;   // first 8192 B = rows 0..31
        const char* g2 = (const char*)Wd2;
        const char* g3 = (const char*)Wd3;
#pragma unroll
        for (int i = 0; i < 8; i++) {
            const int off = (s + 64 * i) * 16;
            cp16(a1 + off, g1 + off);
            cp16(a2 + off, g2 + off);
        }
#pragma unroll
        for (int i = 0; i < 4; i++) {
            const int off = (s + 64 * i) * 16;
            cp16(a3 + off, g3 + off);
        }
        if (s < 8)
            cp16((uint32_t)__cvta_generic_to_shared(sB2) + s * 16,
                 (const char*)bd2 + s * 16);
        else if (s < 16)
            cp16((uint32_t)__cvta_generic_to_shared(sB3) + (s - 8) * 16,
                 (const char*)bd3 + (s - 8) * 16);
        asm volatile("cp.async.commit_group;" ::: "memory");
        asm volatile("cp.async.wait_group 0;" ::: "memory");
    } else if (tid < 64) {
        // c1[tid] = row-invariant part of layer 1.
        const float tt = t[0];
        float hid[16];
#pragma unroll
        for (int i = 0; i < 16; i++)
            hid[i] = fmaxf(fmaf(tt, Wt1[i], bt1[i]), 0.f);

        float s = bd1[tid];
#pragma unroll
        for (int ii = 0; ii < 16; ii++) {
            float tv = bt2[ii];
#pragma unroll
            for (int i = 0; i < 16; i++)
                tv = fmaf(hid[i], Wt2[i * 16 + ii], tv);
            s = fmaf(tv, Wd1[(40 + ii) * 64 + tid], s);
        }
#pragma unroll
        for (int p = 0; p < 8; p++)
            s = fmaf(person[p], Wd1[(32 + p) * 64 + tid], s);
        sC1f[tid] = s;
    }
    __syncthreads();

    const ull* sC1 = (const ull*)sC1f;

    const int rl = tid & 127;   // local row (pairs with rl+128)
    const int ch = tid >> 7;    // column half (uniform per warp)
    const int rA = blockIdx.x * 256 + rl;
    const int rB = rA + 128;
    const bool vA = (rA < n);
    const bool vB = (rB < n);
    const float4* zA4 = (const float4*)(ze + (size_t)rA * 32);
    const float4* zB4 = (const float4*)(ze + (size_t)rB * 32);

    // ---- Layer 1: h1 cols [32ch, 32ch+32) for rows A,B ----
    ull accA[16], accB[16];
#pragma unroll
    for (int j = 0; j < 16; j++) { accA[j] = sC1[ch * 16 + j]; accB[j] = accA[j]; }

#pragma unroll
    for (int c = 0; c < 8; c++) {
        float4 a = make_float4(0.f, 0.f, 0.f, 0.f), b = a;
        if (vA) a = zA4[c];
        if (vB) b = zB4[c];
        const float za[4] = {a.x, a.y, a.z, a.w};
        const float zb[4] = {b.x, b.y, b.z, b.w};
#pragma unroll
        for (int k = 0; k < 4; k++) {
            const int kg = c * 4 + k;
            const ull sA = pack2(za[k], za[k]);
            const ull sB = pack2(zb[k], zb[k]);
            const ulonglong2* wr =
                (const ulonglong2*)(sW1 + kg * 32 + ch * 16);
#pragma unroll
            for (int q = 0; q < 8; q++) {
                const ulonglong2 w = wr[q];
                accA[2 * q]     = fma2(sA, w.x, accA[2 * q]);
                accA[2 * q + 1] = fma2(sA, w.y, accA[2 * q + 1]);
                accB[2 * q]     = fma2(sB, w.x, accB[2 * q]);
                accB[2 * q + 1] = fma2(sB, w.y, accB[2 * q + 1]);
            }
        }
    }

    // relu + exchange h1 (buffer [256 rows][34 ull], my half at ull 16ch..)
    {
        ulonglong2* dA = (ulonglong2*)(sX + rl * 34 + ch * 16);
        ulonglong2* dB = (ulonglong2*)(sX + (rl + 128) * 34 + ch * 16);
#pragma unroll
        for (int q = 0; q < 8; q++) {
            const float2 a0 = unpack2(accA[2 * q]);
            const float2 a1 = unpack2(accA[2 * q + 1]);
            const float2 b0 = unpack2(accB[2 * q]);
            const float2 b1 = unpack2(accB[2 * q + 1]);
            ulonglong2 va, vb;
            va.x = pack2(fmaxf(a0.x, 0.f), fmaxf(a0.y, 0.f));
            va.y = pack2(fmaxf(a1.x, 0.f), fmaxf(a1.y, 0.f));
            vb.x = pack2(fmaxf(b0.x, 0.f), fmaxf(b0.y, 0.f));
            vb.y = pack2(fmaxf(b1.x, 0.f), fmaxf(b1.y, 0.f));
            dA[q] = va;
            dB[q] = vb;
        }
    }
    __syncthreads();

    // ---- Layer 2: h2 cols [16ch, 16ch+16), k over all 64 h1 cols ----
    ull hA[8], hB[8];
#pragma unroll
    for (int j = 0; j < 8; j++) { hA[j] = sB2[ch * 8 + j]; hB[j] = hA[j]; }

    {
        const ull* hbA = sX + rl * 34;
        const ull* hbB = sX + (rl + 128) * 34;
#pragma unroll
        for (int kk = 0; kk < 32; kk++) {
            const float2 fa = unpack2(hbA[kk]);
            const float2 fb = unpack2(hbB[kk]);
#pragma unroll
            for (int sub = 0; sub < 2; sub++) {
                const float va = (sub == 0) ? fa.x : fa.y;
                const float vb = (sub == 0) ? fb.x : fb.y;
                const ull sA = pack2(va, va);
                const ull sB = pack2(vb, vb);
                const ulonglong2* wr =
                    (const ulonglong2*)(sW2 + (2 * kk + sub) * 16 + ch * 8);
#pragma unroll
                for (int q = 0; q < 4; q++) {
                    const ulonglong2 w = wr[q];
                    hA[2 * q]     = fma2(sA, w.x, hA[2 * q]);
                    hA[2 * q + 1] = fma2(sA, w.y, hA[2 * q + 1]);
                    hB[2 * q]     = fma2(sB, w.x, hB[2 * q]);
                    hB[2 * q + 1] = fma2(sB, w.y, hB[2 * q + 1]);
                }
            }
        }
    }
    __syncthreads();   // all h1 reads complete before buffer reuse

    // relu + exchange h2 (reuse sX at stride 18 ull, my quarter at 8ch..)
    {
        ulonglong2* dA = (ulonglong2*)(sX + rl * 18 + ch * 8);
        ulonglong2* dB = (ulonglong2*)(sX + (rl + 128) * 18 + ch * 8);
#pragma unroll
        for (int q = 0; q < 4; q++) {
            const float2 a0 = unpack2(hA[2 * q]);
            const float2 a1 = unpack2(hA[2 * q + 1]);
            const float2 b0 = unpack2(hB[2 * q]);
            const float2 b1 = unpack2(hB[2 * q + 1]);
            ulonglong2 va, vb;
            va.x = pack2(fmaxf(a0.x, 0.f), fmaxf(a0.y, 0.f));
            va.y = pack2(fmaxf(a1.x, 0.f), fmaxf(a1.y, 0.f));
            vb.x = pack2(fmaxf(b0.x, 0.f), fmaxf(b0.y, 0.f));
            vb.y = pack2(fmaxf(b1.x, 0.f), fmaxf(b1.y, 0.f));
            dA[q] = va;
            dB[q] = vb;
        }
    }
    __syncthreads();

    // ---- Layer 3: out cols [16ch, 16ch+16), k over all 32 h2 cols ----
    ull oA[8], oB[8];
#pragma unroll
    for (int j = 0; j < 8; j++) { oA[j] = sB3[ch * 8 + j]; oB[j] = oA[j]; }

    {
        const ull* hbA = sX + rl * 18;
        const ull* hbB = sX + (rl + 128) * 18;
#pragma unroll
        for (int kk = 0; kk < 16; kk++) {
            const float2 fa = unpack2(hbA[kk]);
            const float2 fb = unpack2(hbB[kk]);
#pragma unroll
            for (int sub = 0; sub < 2; sub++) {
                const float va = (sub == 0) ? fa.x : fa.y;
                const float vb = (sub == 0) ? fb.x : fb.y;
                const ull sA = pack2(va, va);
                const ull sB = pack2(vb, vb);
                const ulonglong2* wr =
                    (const ulonglong2*)(sW3 + (2 * kk + sub) * 16 + ch * 8);
#pragma unroll
                for (int q = 0; q < 4; q++) {
                    const ulonglong2 w = wr[q];
                    oA[2 * q]     = fma2(sA, w.x, oA[2 * q]);
                    oA[2 * q + 1] = fma2(sA, w.y, oA[2 * q + 1]);
                    oB[2 * q]     = fma2(sB, w.x, oB[2 * q]);
                    oB[2 * q + 1] = fma2(sB, w.y, oB[2 * q + 1]);
                }
            }
        }
    }

    if (vA) {
        ulonglong2* p = (ulonglong2*)(out + (size_t)rA * 32 + ch * 16);
#pragma unroll
        for (int q = 0; q < 4; q++)
            p[q] = make_ulonglong2(oA[2 * q], oA[2 * q + 1]);
    }
    if (vB) {
        ulonglong2* p = (ulonglong2*)(out + (size_t)rB * 32 + ch * 16);
#pragma unroll
        for (int q = 0; q < 4; q++)
            p[q] = make_ulonglong2(oB[2 * q], oB[2 * q + 1]);
    }
}

// ---------------------------------------------------------------------------
// Inputs: 0 t, 1 zone_embedding, 2 zone_features, 3 person_attrs,
// 4 edge_index, 5 W1, 6 b1, 7 W2, 8 b2, 9 Wt1, 10 bt1, 11 Wt2, 12 bt2,
// 13 Wd1, 14 bd1, 15 Wd2, 16 bd2, 17 Wd3, 18 bd3.  Output [n,32] f32.
// ---------------------------------------------------------------------------
extern "C" void kernel_launch(void* const* d_in, const int* in_sizes, int n_in,
                              void* d_out, int out_size)
{
    const float* t      = (const float*)d_in[0];
    const float* ze     = (const float*)d_in[1];
    const float* person = (const float*)d_in[3];
    const float* Wt1    = (const float*)d_in[9];
    const float* bt1    = (const float*)d_in[10];
    const float* Wt2    = (const float*)d_in[11];
    const float* bt2    = (const float*)d_in[12];
    const float* Wd1    = (const float*)d_in[13];
    const float* bd1    = (const float*)d_in[14];
    const float* Wd2    = (const float*)d_in[15];
    const float* bd2    = (const float*)d_in[16];
    const float* Wd3    = (const float*)d_in[17];
    const float* bd3    = (const float*)d_in[18];
    float* out = (float*)d_out;

    // Raise dynamic-smem cap (host-side, idempotent, executes outside the
    // captured stream work; no allocation involved).
    cudaFuncSetAttribute(zone_split_kernel,
                         cudaFuncAttributeMaxDynamicSharedMemorySize,
                         SMEM_TOTAL);

    const int n = in_sizes[1] / 32;
    const int blocks = (n + 255) / 256;

    zone_split_kernel<<<blocks, 256, SMEM_TOTAL>>>(
        ze, t, person, Wt1, bt1, Wt2, bt2,
        Wd1, bd1, Wd2, bd2, Wd3, bd3, out, n);
}